// round 5
// baseline (speedup 1.0000x reference)
#include <cuda_runtime.h>

#define NWARP 8
#define NTHR  (NWARP*32)

// ---------------------------------------------------------------------------
// Compile-time geometric algebra for Cl(3,0,1), METRIC=(0,1,1,1).
// ---------------------------------------------------------------------------
__host__ __device__ constexpr int ga_popc(int x){ return (x&1)+((x>>1)&1)+((x>>2)&1)+((x>>3)&1); }
__host__ __device__ constexpr int ga_mask(int i){
    return i==0?0: i==1?1: i==2?2: i==3?4: i==4?8: i==5?3: i==6?5: i==7?9:
           i==8?6: i==9?10: i==10?12: i==11?7: i==12?11: i==13?13: i==14?14: 15;
}
__host__ __device__ constexpr int ga_idx(int m){
    return m==0?0: m==1?1: m==2?2: m==4?3: m==8?4: m==3?5: m==5?6: m==9?7:
           m==6?8: m==10?9: m==12?10: m==7?11: m==11?12: m==13?13: m==14?14: 15;
}
__host__ __device__ constexpr int ga_grade(int i){ return ga_popc(ga_mask(i)); }
__host__ __device__ constexpr int ga_csign(int a, int b){
    int s = 0;
    for (int i = 0; i < 4; ++i) if ((b>>i)&1) s += ga_popc(a >> (i+1));
    return (s&1) ? -1 : 1;
}
__host__ __device__ constexpr int ga_dsign(int b){ return ga_csign(ga_mask(b), 15 ^ ga_mask(b)); }

struct GaTabs {
    signed char gs[16][16]; signed char gi[16][16];
    signed char js[16][16]; signed char ja[16][16];
};
__host__ __device__ constexpr GaTabs ga_make(){
    GaTabs t{};
    for (int j = 0; j < 16; ++j)
        for (int k = 0; k < 16; ++k){
            int mj = ga_mask(j), mk = ga_mask(k);
            if (mj & mk & 1){ t.gs[j][k] = 0; t.gi[j][k] = 0; }
            else { t.gs[j][k] = (signed char)ga_csign(mj, mk); t.gi[j][k] = (signed char)ga_idx(mj ^ mk); }
            int jm = 15 ^ mj, km = 15 ^ mk;
            if (jm & km){ t.js[j][k] = 0; t.ja[j][k] = 0; }
            else {
                int im = jm ^ km;
                int s = ga_csign(im, 15 ^ im) * ga_csign(jm, km) * ga_dsign(j) * ga_dsign(k);
                t.js[j][k] = (signed char)s;
                t.ja[j][k] = (signed char)ga_idx(15 ^ im);
            }
        }
    return t;
}

// ---------------------------------------------------------------------------
// packed f32x2 helpers
// ---------------------------------------------------------------------------
typedef unsigned long long u64;
__device__ __forceinline__ u64 pk2(float a, float b){ u64 r; asm("mov.b64 %0,{%1,%2};":"=l"(r):"f"(a),"f"(b)); return r; }
__device__ __forceinline__ void unpk2(u64 v, float& a, float& b){ asm("mov.b64 {%0,%1},%2;":"=f"(a),"=f"(b):"l"(v)); }
__device__ __forceinline__ u64 dup2(float a){ u64 r; asm("mov.b64 %0,{%1,%1};":"=l"(r):"f"(a)); return r; }
__device__ __forceinline__ u64 fma2(u64 a, u64 b, u64 c){ u64 d; asm("fma.rn.f32x2 %0,%1,%2,%3;":"=l"(d):"l"(a),"l"(b),"l"(c)); return d; }
__device__ __forceinline__ u64 mul2(u64 a, u64 b){ u64 d; asm("mul.rn.f32x2 %0,%1,%2;":"=l"(d):"l"(a),"l"(b)); return d; }
__device__ __forceinline__ u64 neg2(u64 a){ return a ^ 0x8000000080000000ull; }

// apply basis map B to packed accumulators (compile-time B)
template<int B>
__device__ __forceinline__ void apply_b2(float wa, float wb, const u64* x2, u64* a0, u64* a1){
    u64 w0 = dup2(wa), w1 = dup2(wb);
    #pragma unroll
    for (int j = 0; j < 16; ++j){
        if (B < 5){
            if (ga_grade(j) == B){ a0[j] = fma2(w0, x2[j], a0[j]); a1[j] = fma2(w1, x2[j], a1[j]); }
        } else {
            if (!(ga_mask(j)&1) && ga_grade(j) == B-5){
                const int jj = ga_idx(ga_mask(j)|1);
                a0[jj] = fma2(w0, x2[j], a0[jj]); a1[jj] = fma2(w1, x2[j], a1[jj]);
            }
        }
    }
}
template<int B>
__device__ __forceinline__ void apply_b1(float wv, const u64* x2, u64* a){
    u64 w = dup2(wv);
    #pragma unroll
    for (int j = 0; j < 16; ++j){
        if (B < 5){
            if (ga_grade(j) == B) a[j] = fma2(w, x2[j], a[j]);
        } else {
            if (!(ga_mask(j)&1) && ga_grade(j) == B-5){
                const int jj = ga_idx(ga_mask(j)|1);
                a[jj] = fma2(w, x2[j], a[jj]);
            }
        }
    }
}

// ---------------------------------------------------------------------------
// smem layout (floats)
// ---------------------------------------------------------------------------
#define OFF_WMV   0
#define OFF_WS    (OFF_WMV + 18432)
#define OFF_WOM   (OFF_WS  + 4096)
#define OFF_WS2M  (OFF_WOM + 9216)
#define OFF_WM2S  (OFF_WS2M+ 2048)
#define OFF_WS2S  (OFF_WM2S+ 2048)
#define OFF_STG   (OFF_WS2S+ 4096)
#define SMEMF (OFF_STG + NWARP*2048)

__global__ void __launch_bounds__(NTHR, 1)
fused_kernel(const float* __restrict__ mv, const float* __restrict__ refmv,
             const float* __restrict__ sc,
             const float* __restrict__ wLmv, const float* __restrict__ wLs,
             const float* __restrict__ wRmv, const float* __restrict__ wRs,
             const float* __restrict__ wJLmv, const float* __restrict__ wJLs,
             const float* __restrict__ wJRmv, const float* __restrict__ wJRs,
             const float* __restrict__ wOmv,  const float* __restrict__ wOs2mv,
             const float* __restrict__ wM2s,  const float* __restrict__ wS2s,
             float* __restrict__ out, int quadsTotal, int P)
{
    extern __shared__ float sm[];
    const int tid  = threadIdx.x;
    const int warp = tid >> 5;
    const int lane = tid & 31;

    // ---------------- weight repacks ----------------
    {
        const float* wsrc[4] = { wLmv, wRmv, wJLmv, wJRmv };
        for (int idx = tid; idx < 18432; idx += NTHR){
            int i = idx / 576, rem = idx % 576;
            int l, r, b;
            if (rem < 512){ int q = rem >> 7, rr = rem & 127; l = rr >> 2; int c = rr & 3; b = 2*q + (c>>1); r = c & 1; }
            else          { int rr = rem - 512; l = rr >> 1; r = rr & 1; b = 8; }
            int t = (l < 16) ? r : 2 + r;
            int o = l & 15;
            sm[OFF_WMV + idx] = wsrc[t][(o*32 + i)*9 + b];
        }
        const float* ssrc[4] = { wLs, wRs, wJLs, wJRs };
        for (int idx = tid; idx < 4096; idx += NTHR){
            int s2 = idx >> 7, rr = idx & 127, l = rr >> 2, c = rr & 3;
            int r = c & 1, se = c >> 1;
            int t = (l < 16) ? r : 2 + r;
            int o = l & 15;
            sm[OFF_WS + idx] = ssrc[t][o*64 + s2*2 + se];
        }
        for (int idx = tid; idx < 9216; idx += NTHR){
            int i = idx / 288, rem = idx % 288;
            int l, b;
            if (rem < 256){ int q = rem >> 7, rr = rem & 127; l = rr >> 2; b = 4*q + (rr & 3); }
            else          { l = rem - 256; b = 8; }
            sm[OFF_WOM + idx] = wOmv[(l*32 + i)*9 + b];
        }
        for (int idx = tid; idx < 2048; idx += NTHR){
            int se = idx & 1, o = (idx >> 1) & 31, s2 = idx >> 6;
            sm[OFF_WS2M + idx] = wOs2mv[o*64 + s2*2 + se];
        }
        for (int idx = tid; idx < 2048; idx += NTHR){
            int c2 = idx >> 7, rr = idx & 127, l = rr >> 2, c4 = rr & 3;
            int r = c4 & 1, ce = c4 >> 1;
            sm[OFF_WM2S + idx] = wM2s[(l + 32*r)*32 + c2*2 + ce];
        }
        for (int idx = tid; idx < 4096; idx += NTHR){
            int s2 = idx >> 7, rr = idx & 127, l = rr >> 2, c4 = rr & 3;
            int r = c4 & 1, se = c4 >> 1;
            sm[OFF_WS2S + idx] = wS2s[(l + 32*r)*64 + s2*2 + se];
        }
    }
    __syncthreads();

    float* xs = sm + OFF_STG + warp * 2048;
    float* outs = out + (size_t)P * 512;
    const int gwarps = gridDim.x * NWARP;
    constexpr GaTabs T = ga_make();

    for (int quad = blockIdx.x*NWARP + warp; quad < quadsTotal; quad += gwarps){
        const int p0 = quad * 4;
        const float2* sp0 = (const float2*)(sc + (size_t)(p0+0)*64);
        const float2* sp1 = (const float2*)(sc + (size_t)(p0+1)*64);
        const float2* sp2 = (const float2*)(sc + (size_t)(p0+2)*64);
        const float2* sp3 = (const float2*)(sc + (size_t)(p0+3)*64);

        __syncwarp();
        // stage x: rows [i][8 groups of 4 floats], group p at slot (p+i)&7
        #pragma unroll
        for (int pk = 0; pk < 2; ++pk){
            const int pa = p0 + 2*pk;
            const float4* sA = (const float4*)(mv + (size_t)pa * 512);
            const float4* sB = sA + 128;
            float* xsp = xs + pk*1024;
            #pragma unroll
            for (int k = 0; k < 4; ++k){
                int q = lane + 32*k;
                float4 a = sA[q], b = sB[q];
                int i = q >> 2, gp = (q & 3) * 2;
                int s0 = (gp + i) & 7, s1 = (gp + 1 + i) & 7;
                *(ulonglong2*)(xsp + i*32 + s0*4) = make_ulonglong2(pk2(a.x,b.x), pk2(a.y,b.y));
                *(ulonglong2*)(xsp + i*32 + s1*4) = make_ulonglong2(pk2(a.z,b.z), pk2(a.w,b.w));
            }
        }
        __syncwarp();

        // phase 1: 4 equi_linears for 4 positions
        u64 acc0[2][16], acc1[2][16];
        #pragma unroll
        for (int pk = 0; pk < 2; ++pk)
            #pragma unroll
            for (int j = 0; j < 16; ++j){ acc0[pk][j] = 0ull; acc1[pk][j] = 0ull; }

        #pragma unroll 1
        for (int i = 0; i < 32; ++i){
            const float* wp = sm + OFF_WMV + i*576;
            float4 f0 = ((const float4*)(wp      ))[lane];
            float4 f1 = ((const float4*)(wp + 128))[lane];
            float4 f2 = ((const float4*)(wp + 256))[lane];
            float4 f3 = ((const float4*)(wp + 384))[lane];
            float w8a, w8b; unpk2(((const u64*)(wp + 512))[lane], w8a, w8b);
            #pragma unroll
            for (int pk = 0; pk < 2; ++pk){
                u64 x2[16];
                const float* xp = xs + pk*1024 + i*32;
                #pragma unroll
                for (int p = 0; p < 8; ++p){
                    ulonglong2 v = *(const ulonglong2*)(xp + ((p + i)&7)*4);
                    x2[2*p] = v.x; x2[2*p+1] = v.y;
                }
                apply_b2<0>(f0.x, f0.y, x2, acc0[pk], acc1[pk]);
                apply_b2<1>(f0.z, f0.w, x2, acc0[pk], acc1[pk]);
                apply_b2<2>(f1.x, f1.y, x2, acc0[pk], acc1[pk]);
                apply_b2<3>(f1.z, f1.w, x2, acc0[pk], acc1[pk]);
                apply_b2<4>(f2.x, f2.y, x2, acc0[pk], acc1[pk]);
                apply_b2<5>(f2.z, f2.w, x2, acc0[pk], acc1[pk]);
                apply_b2<6>(f3.x, f3.y, x2, acc0[pk], acc1[pk]);
                apply_b2<7>(f3.z, f3.w, x2, acc0[pk], acc1[pk]);
                apply_b2<8>(w8a,  w8b,  x2, acc0[pk], acc1[pk]);
            }
        }

        // scalar contribution into component 0 (scalars via uniform LDG)
        #pragma unroll 4
        for (int s2 = 0; s2 < 32; ++s2){
            float4 w = ((const float4*)(sm + OFF_WS + s2*128))[lane];
            float2 va = __ldg(sp0 + s2), vb = __ldg(sp1 + s2);
            float2 vc = __ldg(sp2 + s2), vd = __ldg(sp3 + s2);
            u64 e01 = pk2(va.x, vb.x), o01 = pk2(va.y, vb.y);
            u64 e23 = pk2(vc.x, vd.x), o23 = pk2(vc.y, vd.y);
            acc0[0][0] = fma2(dup2(w.x), e01, acc0[0][0]);
            acc1[0][0] = fma2(dup2(w.y), e01, acc1[0][0]);
            acc0[0][0] = fma2(dup2(w.z), o01, acc0[0][0]);
            acc1[0][0] = fma2(dup2(w.w), o01, acc1[0][0]);
            acc0[1][0] = fma2(dup2(w.x), e23, acc0[1][0]);
            acc1[1][0] = fma2(dup2(w.y), e23, acc1[1][0]);
            acc0[1][0] = fma2(dup2(w.z), o23, acc0[1][0]);
            acc1[1][0] = fma2(dup2(w.w), o23, acc1[1][0]);
        }

        // bilinears; store h into staging (swizzled)
        #pragma unroll
        for (int pk = 0; pk < 2; ++pk){
            const int pa = p0 + 2*pk;
            u64 h2[16];
            #pragma unroll
            for (int j = 0; j < 16; ++j) h2[j] = 0ull;

            if (lane < 16){
                #pragma unroll
                for (int j = 0; j < 16; ++j)
                    #pragma unroll
                    for (int k = 0; k < 16; ++k)
                        if (T.gs[j][k] != 0){
                            u64 a = (T.gs[j][k] > 0) ? acc0[pk][j] : neg2(acc0[pk][j]);
                            h2[T.gi[j][k]] = fma2(a, acc1[pk][k], h2[T.gi[j][k]]);
                        }
            } else {
                u64 lam2 = pk2(__ldg(refmv + (size_t)pa*16 + 15), __ldg(refmv + (size_t)(pa+1)*16 + 15));
                #pragma unroll
                for (int j = 0; j < 16; ++j)
                    #pragma unroll
                    for (int k = 0; k < 16; ++k)
                        if (T.js[j][k] != 0){
                            u64 a = (T.js[j][k] > 0) ? acc0[pk][j] : neg2(acc0[pk][j]);
                            h2[T.ja[j][k]] = fma2(a, acc1[pk][k], h2[T.ja[j][k]]);
                        }
                #pragma unroll
                for (int j = 0; j < 16; ++j) h2[j] = mul2(h2[j], lam2);
            }
            float* hr = xs + pk*1024 + lane*32;
            #pragma unroll
            for (int p = 0; p < 8; ++p)
                *(ulonglong2*)(hr + ((p + lane)&7)*4) = make_ulonglong2(h2[2*p], h2[2*p+1]);
        }
        __syncwarp();

        // phase 2: output equi_linear (o = lane)
        u64 ao[2][16];
        #pragma unroll
        for (int pk = 0; pk < 2; ++pk)
            #pragma unroll
            for (int j = 0; j < 16; ++j) ao[pk][j] = 0ull;

        #pragma unroll 1
        for (int i = 0; i < 32; ++i){
            const float* wp = sm + OFF_WOM + i*288;
            float4 g0 = ((const float4*)(wp      ))[lane];
            float4 g1 = ((const float4*)(wp + 128))[lane];
            float wb8 = wp[256 + lane];
            #pragma unroll
            for (int pk = 0; pk < 2; ++pk){
                u64 x2[16];
                const float* xp = xs + pk*1024 + i*32;
                #pragma unroll
                for (int p = 0; p < 8; ++p){
                    ulonglong2 v = *(const ulonglong2*)(xp + ((p + i)&7)*4);
                    x2[2*p] = v.x; x2[2*p+1] = v.y;
                }
                apply_b1<0>(g0.x, x2, ao[pk]);
                apply_b1<1>(g0.y, x2, ao[pk]);
                apply_b1<2>(g0.z, x2, ao[pk]);
                apply_b1<3>(g0.w, x2, ao[pk]);
                apply_b1<4>(g1.x, x2, ao[pk]);
                apply_b1<5>(g1.y, x2, ao[pk]);
                apply_b1<6>(g1.z, x2, ao[pk]);
                apply_b1<7>(g1.w, x2, ao[pk]);
                apply_b1<8>(wb8,  x2, ao[pk]);
            }
        }

        // scalars into component 0 (weights from smem WS2M)
        #pragma unroll 4
        for (int s2 = 0; s2 < 32; ++s2){
            float we, wo; unpk2(*(const u64*)(sm + OFF_WS2M + (s2*32 + lane)*2), we, wo);
            float2 va = __ldg(sp0 + s2), vb = __ldg(sp1 + s2);
            float2 vc = __ldg(sp2 + s2), vd = __ldg(sp3 + s2);
            u64 dwe = dup2(we), dwo = dup2(wo);
            ao[0][0] = fma2(dwe, pk2(va.x, vb.x), ao[0][0]);
            ao[0][0] = fma2(dwo, pk2(va.y, vb.y), ao[0][0]);
            ao[1][0] = fma2(dwe, pk2(vc.x, vd.x), ao[1][0]);
            ao[1][0] = fma2(dwo, pk2(vc.y, vd.y), ao[1][0]);
        }

        // store out_mv (4 positions)
        #pragma unroll
        for (int pk = 0; pk < 2; ++pk){
            const int pa = p0 + 2*pk;
            float v0[16], v1[16];
            #pragma unroll
            for (int j = 0; j < 16; ++j) unpk2(ao[pk][j], v0[j], v1[j]);
            float* op0 = out + ((size_t)pa*32 + lane)*16;
            float* op1 = op0 + 512;
            #pragma unroll
            for (int j = 0; j < 16; j += 4){
                *(float4*)(op0 + j) = make_float4(v0[j], v0[j+1], v0[j+2], v0[j+3]);
                *(float4*)(op1 + j) = make_float4(v1[j], v1[j+1], v1[j+2], v1[j+3]);
            }
        }

        // out_s: lane owns outputs (lane, lane+32)
        u64 as[2][2] = {{0ull,0ull},{0ull,0ull}};
        #pragma unroll
        for (int c2 = 0; c2 < 16; ++c2){
            float4 w = ((const float4*)(sm + OFF_WM2S + c2*128))[lane];
            u64 dwx = dup2(w.x), dwy = dup2(w.y), dwz = dup2(w.z), dww = dup2(w.w);
            const int re = 2*c2, ro = 2*c2 + 1;
            #pragma unroll
            for (int pk = 0; pk < 2; ++pk){
                u64 hev = *(const u64*)(xs + pk*1024 + re*32 + (re&7)*4);
                u64 hod = *(const u64*)(xs + pk*1024 + ro*32 + (ro&7)*4);
                as[pk][0] = fma2(dwx, hev, as[pk][0]);
                as[pk][1] = fma2(dwy, hev, as[pk][1]);
                as[pk][0] = fma2(dwz, hod, as[pk][0]);
                as[pk][1] = fma2(dww, hod, as[pk][1]);
            }
        }
        #pragma unroll 4
        for (int s2 = 0; s2 < 32; ++s2){
            float4 w = ((const float4*)(sm + OFF_WS2S + s2*128))[lane];
            float2 va = __ldg(sp0 + s2), vb = __ldg(sp1 + s2);
            float2 vc = __ldg(sp2 + s2), vd = __ldg(sp3 + s2);
            u64 e01 = pk2(va.x, vb.x), o01 = pk2(va.y, vb.y);
            u64 e23 = pk2(vc.x, vd.x), o23 = pk2(vc.y, vd.y);
            as[0][0] = fma2(dup2(w.x), e01, as[0][0]);
            as[0][1] = fma2(dup2(w.y), e01, as[0][1]);
            as[0][0] = fma2(dup2(w.z), o01, as[0][0]);
            as[0][1] = fma2(dup2(w.w), o01, as[0][1]);
            as[1][0] = fma2(dup2(w.x), e23, as[1][0]);
            as[1][1] = fma2(dup2(w.y), e23, as[1][1]);
            as[1][0] = fma2(dup2(w.z), o23, as[1][0]);
            as[1][1] = fma2(dup2(w.w), o23, as[1][1]);
        }
        #pragma unroll
        for (int pk = 0; pk < 2; ++pk){
            const int pa = p0 + 2*pk;
            float a0, a1, b0, b1;
            unpk2(as[pk][0], a0, a1);
            unpk2(as[pk][1], b0, b1);
            outs[(size_t)pa*64 + lane]          = a0;
            outs[(size_t)(pa+1)*64 + lane]      = a1;
            outs[(size_t)pa*64 + 32 + lane]     = b0;
            outs[(size_t)(pa+1)*64 + 32 + lane] = b1;
        }
    }
}

// ---------------------------------------------------------------------------
// launch
// ---------------------------------------------------------------------------
extern "C" void kernel_launch(void* const* d_in, const int* in_sizes, int n_in,
                              void* d_out, int out_size)
{
    const float* mv    = (const float*)d_in[0];
    const float* refmv = (const float*)d_in[1];
    const float* sc    = (const float*)d_in[2];
    const float* wLmv  = (const float*)d_in[6];
    const float* wLs   = (const float*)d_in[7];
    const float* wRmv  = (const float*)d_in[8];
    const float* wRs   = (const float*)d_in[9];
    const float* wJLmv = (const float*)d_in[10];
    const float* wJLs  = (const float*)d_in[11];
    const float* wJRmv = (const float*)d_in[12];
    const float* wJRs  = (const float*)d_in[13];
    const float* wOmv  = (const float*)d_in[14];
    const float* wOs2m = (const float*)d_in[15];
    const float* wM2s  = (const float*)d_in[16];
    const float* wS2s  = (const float*)d_in[17];
    float* out = (float*)d_out;

    const int P = in_sizes[0] / (32 * 16);
    const int quads = P / 4;

    int sms = 148;
    cudaDeviceGetAttribute(&sms, cudaDevAttrMultiProcessorCount, 0);

    const size_t smem = (size_t)SMEMF * sizeof(float);
    cudaFuncSetAttribute(fused_kernel, cudaFuncAttributeMaxDynamicSharedMemorySize, (int)smem);

    fused_kernel<<<sms, NTHR, smem>>>(mv, refmv, sc,
                                      wLmv, wLs, wRmv, wRs,
                                      wJLmv, wJLs, wJRmv, wJRs,
                                      wOmv, wOs2m, wM2s, wS2s,
                                      out, quads, P);
}